// round 14
// baseline (speedup 1.0000x reference)
#include <cuda_runtime.h>
#include <cuda_bf16.h>
#include <cstdint>
#include <math.h>

#define H      256
#define E      300
#define S_SENT 1024
#define L_W    64
#define NH3    768
#define NTOPIC 100
#define NTGT   5

typedef unsigned long long u64;

// ---------------- scratch ----------------
__device__ float g_dq[10 * NH3];
__device__ float g_pre[S_SENT * (L_W - 1) * NH3];
__device__ float g_leaf[S_SENT * NH3];
__device__ float g_hA[S_SENT * H];
__device__ float g_hB[S_SENT * H];
__device__ float g_pA[S_SENT * NH3];
__device__ float g_pB[S_SENT * NH3];
__device__ float g_gi[S_SENT * NH3];
__device__ float g_hT[H];

__device__ __forceinline__ float sigf(float x) { return 1.0f / (1.0f + expf(-x)); }

// ---- packed fp32x2 helpers (GRU matvec) ----
__device__ __forceinline__ u64 pk2(float lo, float hi) {
    u64 r; asm("mov.b64 %0, {%1, %2};" : "=l"(r) : "f"(lo), "f"(hi)); return r;
}
__device__ __forceinline__ u64 ffma2(u64 a, u64 b, u64 c) {
    u64 d; asm("fma.rn.f32x2 %0, %1, %2, %3;" : "=l"(d) : "l"(a), "l"(b), "l"(c)); return d;
}
__device__ __forceinline__ float pairsum(u64 v) {
    float x, y; asm("mov.b64 {%0, %1}, %2;" : "=f"(x), "=f"(y) : "l"(v)); return x + y;
}

__device__ __forceinline__ uint32_t tf32_of(float x) {
    uint32_t u; asm("cvt.rna.tf32.f32 %0, %1;" : "=r"(u) : "f"(x)); return u;
}
__device__ __forceinline__ void mma_tf32(float c[4], const uint32_t a[4], const uint32_t b[2]) {
    asm volatile(
        "mma.sync.aligned.m16n8k8.row.col.f32.tf32.tf32.f32 "
        "{%0,%1,%2,%3}, {%4,%5,%6,%7}, {%8,%9}, {%0,%1,%2,%3};"
        : "+f"(c[0]), "+f"(c[1]), "+f"(c[2]), "+f"(c[3])
        : "r"(a[0]), "r"(a[1]), "r"(a[2]), "r"(a[3]), "r"(b[0]), "r"(b[1]));
}

// ---------------- dep-type table ----------------
__global__ void prep_kernel(const float* __restrict__ D, const float* __restrict__ q) {
    __shared__ float qs[H];
    int t = blockIdx.x;
    if (threadIdx.x < H) qs[threadIdx.x] = q[t * H + threadIdx.x];
    __syncthreads();
    int j = threadIdx.x;
    const float* Drow = D + (size_t)j * H;
    float acc = 0.f;
#pragma unroll 8
    for (int k = 0; k < H; k++) acc += Drow[k] * qs[k];
    g_dq[t * NH3 + j] = acc;
}

// ---------------- wx via TF32 mma ----------------
__global__ __launch_bounds__(256) void wx_mma(
    const int* __restrict__ sidx, const int* __restrict__ dep,
    const float* __restrict__ idx2vec, const float* __restrict__ W,
    const float* __restrict__ bias) {
    __shared__ uint32_t As[128][36];
    __shared__ uint32_t Bs[64][36];
    __shared__ int   ridx[128];
    __shared__ int   djs[128];
    __shared__ float bsh[64];
    __shared__ float dqs[10][64];

    int tid = threadIdx.x;
    int wid = tid >> 5, lane = tid & 31;
    int warp_m = wid >> 1, warp_n = wid & 1;
    int lr = lane >> 2, lc = lane & 3;
    int n0 = blockIdx.x * 64, m0 = blockIdx.y * 128;

    if (tid < 128) {
        int m = m0 + tid;
        ridx[tid] = sidx[m];
        int s = m >> 6, l = m & 63;
        djs[tid] = (l == 63) ? 9 : dep[s * 63 + l];
    }
    if (tid < 64) bsh[tid] = bias[n0 + tid];
    for (int e = tid; e < 640; e += 256) {
        int t = e >> 6, c = e & 63;
        dqs[t][c] = g_dq[t * NH3 + n0 + c];
    }
    __syncthreads();

    float c[2][4][4];
#pragma unroll
    for (int mf = 0; mf < 2; mf++)
#pragma unroll
        for (int nf = 0; nf < 4; nf++)
#pragma unroll
            for (int r = 0; r < 4; r++) c[mf][nf][r] = 0.f;

    float4 av[4], bv[2];
    const float4 z4 = make_float4(0.f, 0.f, 0.f, 0.f);

#pragma unroll
    for (int i = 0; i < 4; i++) {
        int idx = tid + 256 * i;
        int m = idx >> 3, k4 = idx & 7;
        int off = k4 * 4;
        av[i] = (off < E) ? *(const float4*)(idx2vec + (size_t)ridx[m] * E + off) : z4;
    }
#pragma unroll
    for (int i = 0; i < 2; i++) {
        int idx = tid + 256 * i;
        int n = idx >> 3, k4 = idx & 7;
        int off = k4 * 4;
        bv[i] = (off < E) ? *(const float4*)(W + (size_t)(n0 + n) * E + off) : z4;
    }

    for (int it = 0; it < 10; it++) {
        __syncthreads();
#pragma unroll
        for (int i = 0; i < 4; i++) {
            int idx = tid + 256 * i;
            int m = idx >> 3, k4 = idx & 7;
            uint32_t* d = &As[m][k4 * 4];
            d[0] = tf32_of(av[i].x); d[1] = tf32_of(av[i].y);
            d[2] = tf32_of(av[i].z); d[3] = tf32_of(av[i].w);
        }
#pragma unroll
        for (int i = 0; i < 2; i++) {
            int idx = tid + 256 * i;
            int n = idx >> 3, k4 = idx & 7;
            uint32_t* d = &Bs[n][k4 * 4];
            d[0] = tf32_of(bv[i].x); d[1] = tf32_of(bv[i].y);
            d[2] = tf32_of(bv[i].z); d[3] = tf32_of(bv[i].w);
        }
        __syncthreads();
        if (it < 9) {
            int kbase = (it + 1) * 32;
#pragma unroll
            for (int i = 0; i < 4; i++) {
                int idx = tid + 256 * i;
                int m = idx >> 3, k4 = idx & 7;
                int off = kbase + k4 * 4;
                av[i] = (off < E) ? *(const float4*)(idx2vec + (size_t)ridx[m] * E + off) : z4;
            }
#pragma unroll
            for (int i = 0; i < 2; i++) {
                int idx = tid + 256 * i;
                int n = idx >> 3, k4 = idx & 7;
                int off = kbase + k4 * 4;
                bv[i] = (off < E) ? *(const float4*)(W + (size_t)(n0 + n) * E + off) : z4;
            }
        }
#pragma unroll
        for (int kf = 0; kf < 4; kf++) {
            int kcol = kf * 8 + lc;
            uint32_t a[2][4], bfr[4][2];
#pragma unroll
            for (int mf = 0; mf < 2; mf++) {
                int bm = warp_m * 32 + mf * 16 + lr;
                a[mf][0] = As[bm][kcol];
                a[mf][1] = As[bm + 8][kcol];
                a[mf][2] = As[bm][kcol + 4];
                a[mf][3] = As[bm + 8][kcol + 4];
            }
#pragma unroll
            for (int nf = 0; nf < 4; nf++) {
                int bn = warp_n * 32 + nf * 8 + lr;
                bfr[nf][0] = Bs[bn][kcol];
                bfr[nf][1] = Bs[bn][kcol + 4];
            }
#pragma unroll
            for (int mf = 0; mf < 2; mf++)
#pragma unroll
                for (int nf = 0; nf < 4; nf++)
                    mma_tf32(c[mf][nf], a[mf], bfr[nf]);
        }
    }

#pragma unroll
    for (int mf = 0; mf < 2; mf++) {
#pragma unroll
        for (int half = 0; half < 2; half++) {
            int ml = warp_m * 32 + mf * 16 + lr + half * 8;
            int m = m0 + ml;
            int s = m >> 6, l = m & 63;
            int dj = djs[ml];
            float* outr = ((l == 63) ? (g_leaf + (size_t)s * NH3)
                                     : (g_pre + (size_t)(s * 63 + l) * NH3)) + n0;
#pragma unroll
            for (int nf = 0; nf < 4; nf++) {
                int col = warp_n * 32 + nf * 8 + 2 * lc;
                float v0 = c[mf][nf][half * 2 + 0] + bsh[col] + dqs[dj][col];
                float v1 = c[mf][nf][half * 2 + 1] + bsh[col + 1] + dqs[dj][col + 1];
                *(float2*)(outr + col) = make_float2(v0, v1);
            }
        }
    }
}

// ---------------- leaf (writes ping buffer A) ----------------
__global__ void leaf_kernel() {
    int idx = blockIdx.x * 256 + threadIdx.x;
    int s = idx >> 8, i = idx & 255;
    const float* r = g_leaf + (size_t)s * NH3;
    g_hA[idx] = tanhf(sigf(r[256 + i]) * tanhf(r[512 + i]));
}

// ---------------- fused tree step (R13) ----------------
__global__ __launch_bounds__(256) void tree_mma(const float* __restrict__ U, int k) {
    __shared__ uint32_t smb[6400];
    uint32_t (*As)[36] = (uint32_t(*)[36])smb;
    uint32_t (*Bs)[36] = (uint32_t(*)[36])(smb + 2304);
    float (*Cs)[100] = (float(*)[100])smb;

    const float* hin = (k & 1) ? g_hB : g_hA;
    float* hout = (k & 1) ? g_hA : g_hB;

    int tid = threadIdx.x;
    int wid = tid >> 5, lane = tid & 31;
    int warp_m = wid >> 2, warp_n = wid & 3;
    int lr = lane >> 2, lc = lane & 3;
    int i0 = blockIdx.x * 32, m0 = blockIdx.y * 64;

    float c[2][3][4];
#pragma unroll
    for (int mf = 0; mf < 2; mf++)
#pragma unroll
        for (int nf = 0; nf < 3; nf++)
#pragma unroll
            for (int r = 0; r < 4; r++) c[mf][nf][r] = 0.f;

    float4 av[2], bv[3];
#pragma unroll
    for (int i = 0; i < 2; i++) {
        int idx = tid + 256 * i;
        int ml = idx >> 3, k4 = idx & 7;
        av[i] = *(const float4*)(hin + (size_t)(m0 + ml) * H + k4 * 4);
    }
#pragma unroll
    for (int i = 0; i < 3; i++) {
        int idx = tid + 256 * i;
        int bl = idx >> 3, k4 = idx & 7;
        int g = bl >> 5, r = bl & 31;
        bv[i] = *(const float4*)(U + (size_t)(g * H + i0 + r) * H + k4 * 4);
    }

    for (int it = 0; it < 8; it++) {
        __syncthreads();
#pragma unroll
        for (int i = 0; i < 2; i++) {
            int idx = tid + 256 * i;
            int ml = idx >> 3, k4 = idx & 7;
            uint32_t* d = &As[ml][k4 * 4];
            d[0] = tf32_of(av[i].x); d[1] = tf32_of(av[i].y);
            d[2] = tf32_of(av[i].z); d[3] = tf32_of(av[i].w);
        }
#pragma unroll
        for (int i = 0; i < 3; i++) {
            int idx = tid + 256 * i;
            int bl = idx >> 3, k4 = idx & 7;
            uint32_t* d = &Bs[bl][k4 * 4];
            d[0] = tf32_of(bv[i].x); d[1] = tf32_of(bv[i].y);
            d[2] = tf32_of(bv[i].z); d[3] = tf32_of(bv[i].w);
        }
        __syncthreads();
        if (it < 7) {
            int kbase = (it + 1) * 32;
#pragma unroll
            for (int i = 0; i < 2; i++) {
                int idx = tid + 256 * i;
                int ml = idx >> 3, k4 = idx & 7;
                av[i] = *(const float4*)(hin + (size_t)(m0 + ml) * H + kbase + k4 * 4);
            }
#pragma unroll
            for (int i = 0; i < 3; i++) {
                int idx = tid + 256 * i;
                int bl = idx >> 3, k4 = idx & 7;
                int g = bl >> 5, r = bl & 31;
                bv[i] = *(const float4*)(U + (size_t)(g * H + i0 + r) * H + kbase + k4 * 4);
            }
        }
#pragma unroll
        for (int kf = 0; kf < 4; kf++) {
            int kcol = kf * 8 + lc;
            uint32_t a[2][4], bfr[3][2];
#pragma unroll
            for (int mf = 0; mf < 2; mf++) {
                int bm = warp_m * 32 + mf * 16 + lr;
                a[mf][0] = As[bm][kcol];
                a[mf][1] = As[bm + 8][kcol];
                a[mf][2] = As[bm][kcol + 4];
                a[mf][3] = As[bm + 8][kcol + 4];
            }
#pragma unroll
            for (int nf = 0; nf < 3; nf++) {
                int bn = warp_n * 24 + nf * 8 + lr;
                bfr[nf][0] = Bs[bn][kcol];
                bfr[nf][1] = Bs[bn][kcol + 4];
            }
#pragma unroll
            for (int mf = 0; mf < 2; mf++)
#pragma unroll
                for (int nf = 0; nf < 3; nf++)
                    mma_tf32(c[mf][nf], a[mf], bfr[nf]);
        }
    }

    __syncthreads();
#pragma unroll
    for (int mf = 0; mf < 2; mf++) {
        int r0 = warp_m * 32 + mf * 16 + lr;
#pragma unroll
        for (int nf = 0; nf < 3; nf++) {
            int colw = warp_n * 24 + nf * 8 + 2 * lc;
            Cs[r0][colw]     = c[mf][nf][0];
            Cs[r0][colw + 1] = c[mf][nf][1];
            Cs[r0 + 8][colw]     = c[mf][nf][2];
            Cs[r0 + 8][colw + 1] = c[mf][nf][3];
        }
    }
    __syncthreads();

    for (int e = tid; e < 64 * 32; e += 256) {
        int ml = e >> 5, ii = e & 31;
        int s = m0 + ml, ig = i0 + ii;
        size_t pb = ((size_t)s * 63 + k) * NH3;
        float t0 = Cs[ml][ii]      + g_pre[pb + ig];
        float t1 = Cs[ml][32 + ii] + g_pre[pb + 256 + ig];
        float t2 = Cs[ml][64 + ii] + g_pre[pb + 512 + ig];
        float hc = hin[(size_t)s * H + ig];
        hout[(size_t)s * H + ig] = tanhf(sigf(t1) * tanhf(t2) + sigf(t0) * hc);
    }
}

// ---------------- gi GEMM (R12 kernel, reads g_hB) ----------------
__global__ __launch_bounds__(256) void ab_mma(const float* __restrict__ B) {
    __shared__ uint32_t As[128][36];
    __shared__ uint32_t Bs[64][36];

    int tid = threadIdx.x;
    int wid = tid >> 5, lane = tid & 31;
    int warp_m = wid >> 1, warp_n = wid & 1;
    int lr = lane >> 2, lc = lane & 3;
    int n0 = blockIdx.x * 64, m0 = blockIdx.y * 128, kb = blockIdx.z * 128;

    float c[2][4][4];
#pragma unroll
    for (int mf = 0; mf < 2; mf++)
#pragma unroll
        for (int nf = 0; nf < 4; nf++)
#pragma unroll
            for (int r = 0; r < 4; r++) c[mf][nf][r] = 0.f;

    for (int it = 0; it < 4; it++) {
        int kbase = kb + it * 32;
        float4 av[4], bv[2];
#pragma unroll
        for (int i = 0; i < 4; i++) {
            int idx = tid + 256 * i;
            int m = idx >> 3, k4 = idx & 7;
            av[i] = *(const float4*)(g_hB + (size_t)(m0 + m) * H + kbase + k4 * 4);
        }
#pragma unroll
        for (int i = 0; i < 2; i++) {
            int idx = tid + 256 * i;
            int n = idx >> 3, k4 = idx & 7;
            bv[i] = *(const float4*)(B + (size_t)(n0 + n) * H + kbase + k4 * 4);
        }
        __syncthreads();
#pragma unroll
        for (int i = 0; i < 4; i++) {
            int idx = tid + 256 * i;
            int m = idx >> 3, k4 = idx & 7;
            uint32_t* d = &As[m][k4 * 4];
            d[0] = tf32_of(av[i].x); d[1] = tf32_of(av[i].y);
            d[2] = tf32_of(av[i].z); d[3] = tf32_of(av[i].w);
        }
#pragma unroll
        for (int i = 0; i < 2; i++) {
            int idx = tid + 256 * i;
            int n = idx >> 3, k4 = idx & 7;
            uint32_t* d = &Bs[n][k4 * 4];
            d[0] = tf32_of(bv[i].x); d[1] = tf32_of(bv[i].y);
            d[2] = tf32_of(bv[i].z); d[3] = tf32_of(bv[i].w);
        }
        __syncthreads();
#pragma unroll
        for (int kf = 0; kf < 4; kf++) {
            int kcol = kf * 8 + lc;
            uint32_t a[2][4], bfr[4][2];
#pragma unroll
            for (int mf = 0; mf < 2; mf++) {
                int bm = warp_m * 32 + mf * 16 + lr;
                a[mf][0] = As[bm][kcol];
                a[mf][1] = As[bm + 8][kcol];
                a[mf][2] = As[bm][kcol + 4];
                a[mf][3] = As[bm + 8][kcol + 4];
            }
#pragma unroll
            for (int nf = 0; nf < 4; nf++) {
                int bn = warp_n * 32 + nf * 8 + lr;
                bfr[nf][0] = Bs[bn][kcol];
                bfr[nf][1] = Bs[bn][kcol + 4];
            }
#pragma unroll
            for (int mf = 0; mf < 2; mf++)
#pragma unroll
                for (int nf = 0; nf < 4; nf++)
                    mma_tf32(c[mf][nf], a[mf], bfr[nf]);
        }
    }

    float* Cw = blockIdx.z ? g_pB : g_pA;
#pragma unroll
    for (int mf = 0; mf < 2; mf++) {
        int r0 = m0 + warp_m * 32 + mf * 16 + lr;
#pragma unroll
        for (int nf = 0; nf < 4; nf++) {
            int col = n0 + warp_n * 32 + nf * 8 + 2 * lc;
            *(float2*)(Cw + (size_t)r0 * NH3 + col) = make_float2(c[mf][nf][0], c[mf][nf][1]);
            *(float2*)(Cw + (size_t)(r0 + 8) * NH3 + col) = make_float2(c[mf][nf][2], c[mf][nf][3]);
        }
    }
}

// ---------------- gi = partials + bih ----------------
__global__ void gi_combine_kernel(const float* __restrict__ bih) {
    int idx = blockIdx.x * 256 + threadIdx.x;
    int n = idx % NH3;
    g_gi[idx] = g_pA[idx] + g_pB[idx] + bih[n];
}

// ---------------- GRU: 8-CTA cluster, pull data-path + mbarrier handshake ----------------
__device__ __forceinline__ uint32_t smem_u32(const void* p) {
    return (uint32_t)__cvta_generic_to_shared(p);
}
__device__ __forceinline__ uint32_t mapa_u32(uint32_t a, uint32_t r) {
    uint32_t o;
    asm("mapa.shared::cluster.u32 %0, %1, %2;" : "=r"(o) : "r"(a), "r"(r));
    return o;
}
__device__ __forceinline__ float ld_remote(uint32_t a) {
    float v;
    asm volatile("ld.shared::cluster.f32 %0, [%1];" : "=f"(v) : "r"(a) : "memory");
    return v;
}
__device__ __forceinline__ void mbar_arrive_remote(uint32_t a) {
    asm volatile("mbarrier.arrive.release.cluster.shared::cluster.b64 _, [%0];"
                 :: "r"(a) : "memory");
}
__device__ __forceinline__ void mbar_wait_parity(uint32_t a, int parity) {
    asm volatile(
        "{\n\t.reg .pred P;\n\t"
        "WL_%=:\n\t"
        "mbarrier.try_wait.parity.acquire.cluster.shared::cta.b64 P, [%0], %1, 0x989680;\n\t"
        "@P bra.uni WD_%=;\n\t"
        "bra.uni WL_%=;\n\t"
        "WD_%=:\n\t}"
        :: "r"(a), "r"((uint32_t)parity) : "memory");
}
__device__ __forceinline__ void cluster_barrier() {
    asm volatile("barrier.cluster.arrive.aligned;" ::: "memory");
    asm volatile("barrier.cluster.wait.aligned;" ::: "memory");
}

__global__ void __cluster_dims__(8, 1, 1) __launch_bounds__(256, 1)
gru_kernel(const float* __restrict__ whh, const float* __restrict__ bhh,
           const float* __restrict__ h0) {
    __shared__ __align__(16) float hsh[H];
    __shared__ float ghsh[2][96];
    __shared__ __align__(8) unsigned long long mbar[2];

    int tid = threadIdx.x;
    unsigned rank;
    asm("mov.u32 %0, %%cluster_ctarank;" : "=r"(rank));
    int g = tid >> 3, p = tid & 7;
    int jbase = (int)rank * 96 + g * 3;

    u64 wp[3][16];
    float bh[3];
#pragma unroll
    for (int c = 0; c < 3; c++) {
        int j = jbase + c;
        bh[c] = bhh[j];
        const float4* wr = (const float4*)(whh + (size_t)j * H + p * 32);
#pragma unroll
        for (int u = 0; u < 8; u++) {
            float4 v = wr[u];
            wp[c][2 * u]     = pk2(v.x, v.y);
            wp[c][2 * u + 1] = pk2(v.z, v.w);
        }
    }
    hsh[tid] = h0[tid];

    if (tid == 0) {
        asm volatile("mbarrier.init.shared.b64 [%0], %1;"
                     :: "r"(smem_u32(&mbar[0])), "r"(8u) : "memory");
        asm volatile("mbarrier.init.shared.b64 [%0], %1;"
                     :: "r"(smem_u32(&mbar[1])), "r"(8u) : "memory");
    }
    __syncthreads();
    cluster_barrier();                 // all barriers initialized before any remote arrive

    // pull addresses (R7): gh[c*256 + tid] lives on rank (j/96) at offset j%96
    uint32_t radr[2][3];
#pragma unroll
    for (int par = 0; par < 2; par++)
#pragma unroll
        for (int c = 0; c < 3; c++) {
            int j = c * H + tid;
            radr[par][c] = mapa_u32(smem_u32(&ghsh[par][j % 96]), (uint32_t)(j / 96));
        }
    // arrive targets (thread 0 only): mbar[par] on every rank
    uint32_t badr[2][8];
    if (tid == 0) {
#pragma unroll
        for (int par = 0; par < 2; par++)
#pragma unroll
            for (int r8 = 0; r8 < 8; r8++)
                badr[par][r8] = mapa_u32(smem_u32(&mbar[par]), (uint32_t)r8);
    }
    uint32_t lbar0 = smem_u32(&mbar[0]), lbar1 = smem_u32(&mbar[1]);
    int ph0 = 0, ph1 = 0;

    for (int t = 0; t < S_SENT; t++) {
        __syncthreads();               // hsh from previous step stable
        int par = t & 1;
        const float* gir = g_gi + (size_t)t * NH3;
        float gi0 = __ldg(gir + tid), gi1 = __ldg(gir + 256 + tid), gi2 = __ldg(gir + 512 + tid);

        u64 hvp[16];
        const float4* hp = (const float4*)(hsh + p * 32);
#pragma unroll
        for (int u = 0; u < 8; u++) {
            float4 v = hp[u];
            hvp[2 * u]     = pk2(v.x, v.y);
            hvp[2 * u + 1] = pk2(v.z, v.w);
        }
        u64 pa0 = 0ull, pa1 = 0ull, pa2 = 0ull;
#pragma unroll
        for (int u = 0; u < 16; u++) {
            pa0 = ffma2(wp[0][u], hvp[u], pa0);
            pa1 = ffma2(wp[1][u], hvp[u], pa1);
            pa2 = ffma2(wp[2][u], hvp[u], pa2);
        }
        float a0 = pairsum(pa0), a1 = pairsum(pa1), a2 = pairsum(pa2);
#pragma unroll
        for (int off = 4; off > 0; off >>= 1) {
            a0 += __shfl_down_sync(0xffffffffu, a0, off, 8);
            a1 += __shfl_down_sync(0xffffffffu, a1, off, 8);
            a2 += __shfl_down_sync(0xffffffffu, a2, off, 8);
        }
        if (p == 0) {
            ghsh[par][g * 3 + 0] = a0 + bh[0];
            ghsh[par][g * 3 + 1] = a1 + bh[1];
            ghsh[par][g * 3 + 2] = a2 + bh[2];
        }
        __syncthreads();               // local gh slice complete
        if (tid == 0) {
#pragma unroll
            for (int r8 = 0; r8 < 8; r8++) mbar_arrive_remote(badr[par][r8]);
        }
        if (par == 0) { mbar_wait_parity(lbar0, ph0); ph0 ^= 1; }
        else          { mbar_wait_parity(lbar1, ph1); ph1 ^= 1; }

        float gh0 = ld_remote(radr[par][0]);
        float gh1 = ld_remote(radr[par][1]);
        float gh2 = ld_remote(radr[par][2]);
        float hh = hsh[tid];
        float r = sigf(gi0 + gh0);
        float z = sigf(gi1 + gh1);
        float n = tanhf(gi2 + r * gh2);
        hsh[tid] = (1.0f - z) * n + z * hh;
    }
    __syncthreads();
    if (rank == 0) g_hT[tid] = hsh[tid];
    cluster_barrier();                 // no CTA exits with remote traffic in flight
}

// ---------------- final: topic, gate, classifier, softmax ----------------
__global__ void final_kernel(const float* __restrict__ DT,
                             const float* __restrict__ gate_W, const float* __restrict__ gate_U,
                             const float* __restrict__ gate_b,
                             const float* __restrict__ mlp_W, const float* __restrict__ mlp_b,
                             const float* __restrict__ out_W, const float* __restrict__ out_b,
                             float* __restrict__ out) {
    __shared__ float tsh[H], hsh[H], vsh[H], lg[NTGT];
    int tid = threadIdx.x;
    float acc = mlp_b[tid];
    const float* mr = mlp_W + (size_t)tid * NTOPIC;
#pragma unroll 4
    for (int k = 0; k < NTOPIC; k++) acc += mr[k] * DT[k];
    tsh[tid] = tanhf(acc);
    hsh[tid] = g_hT[tid];
    __syncthreads();
    float ga = gate_b[tid], gb = gate_b[tid + H];
    const float* wr = gate_W + (size_t)tid * H;
    const float* wr2 = gate_W + (size_t)(tid + H) * H;
    const float* ur = gate_U + (size_t)tid * H;
    const float* ur2 = gate_U + (size_t)(tid + H) * H;
#pragma unroll 4
    for (int k = 0; k < H; k++) {
        float hk = hsh[k], tk = tsh[k];
        ga += wr[k] * hk + ur[k] * tk;
        gb += wr2[k] * hk + ur2[k] * tk;
    }
    vsh[tid] = tanhf(sigf(ga) * hsh[tid] + sigf(gb) * tsh[tid]);
    __syncthreads();
    int wix = tid >> 5, lane = tid & 31;
    if (wix < NTGT) {
        float a = 0.f;
        for (int k = lane; k < H; k += 32) a += out_W[wix * H + k] * vsh[k];
#pragma unroll
        for (int off = 16; off > 0; off >>= 1) a += __shfl_down_sync(0xffffffffu, a, off);
        if (lane == 0) lg[wix] = a + out_b[wix];
    }
    __syncthreads();
    if (tid == 0) {
        float mx = lg[0];
        for (int i = 1; i < NTGT; i++) mx = fmaxf(mx, lg[i]);
        float s = 0.f, e[NTGT];
        for (int i = 0; i < NTGT; i++) { e[i] = expf(lg[i] - mx); s += e[i]; }
        for (int i = 0; i < NTGT; i++) out[i] = e[i] / s;
    }
}

extern "C" void kernel_launch(void* const* d_in, const int* in_sizes, int n_in,
                              void* d_out, int out_size) {
    const int*   sidx    = (const int*)  d_in[0];
    const int*   dep     = (const int*)  d_in[1];
    const float* DT      = (const float*)d_in[2];
    const float* h0      = (const float*)d_in[3];
    const float* idx2vec = (const float*)d_in[4];
    const float* q       = (const float*)d_in[5];
    const float* W       = (const float*)d_in[6];
    const float* U       = (const float*)d_in[7];
    const float* D       = (const float*)d_in[8];
    const float* b       = (const float*)d_in[9];
    const float* gru_wih = (const float*)d_in[10];
    const float* gru_whh = (const float*)d_in[11];
    const float* gru_bih = (const float*)d_in[12];
    const float* gru_bhh = (const float*)d_in[13];
    const float* gate_W  = (const float*)d_in[14];
    const float* gate_U  = (const float*)d_in[15];
    const float* gate_b  = (const float*)d_in[16];
    const float* mlp_W   = (const float*)d_in[17];
    const float* mlp_b   = (const float*)d_in[18];
    const float* out_W   = (const float*)d_in[19];
    const float* out_b   = (const float*)d_in[20];
    float* out = (float*)d_out;

    prep_kernel<<<10, NH3>>>(D, q);
    wx_mma<<<dim3(12, 512), 256>>>(sidx, dep, idx2vec, W, b);
    leaf_kernel<<<1024, 256>>>();

    for (int k = L_W - 2; k >= 0; k--)
        tree_mma<<<dim3(8, 16), 256>>>(U, k);

    ab_mma<<<dim3(12, 8, 2), 256>>>(gru_wih);
    gi_combine_kernel<<<3072, 256>>>(gru_bih);

    gru_kernel<<<8, 256>>>(gru_whh, gru_bhh, h0);

    final_kernel<<<1, 256>>>(DT, gate_W, gate_U, gate_b, mlp_W, mlp_b, out_W, out_b, out);
}

// round 15
// speedup vs baseline: 1.4418x; 1.4418x over previous
#include <cuda_runtime.h>
#include <cuda_bf16.h>
#include <cstdint>
#include <math.h>

#define H      256
#define E      300
#define S_SENT 1024
#define L_W    64
#define NH3    768
#define NTOPIC 100
#define NTGT   5

typedef unsigned long long u64;

// ---------------- scratch ----------------
__device__ float g_dq[10 * NH3];
__device__ float g_pre[S_SENT * (L_W - 1) * NH3];
__device__ float g_leaf[S_SENT * NH3];
__device__ float g_hA[S_SENT * H];
__device__ float g_hB[S_SENT * H];
__device__ float g_pA[S_SENT * NH3];
__device__ float g_pB[S_SENT * NH3];
__device__ float g_gi[S_SENT * NH3];
__device__ float g_hT[H];

__device__ __forceinline__ float sigf(float x) { return 1.0f / (1.0f + expf(-x)); }

// ---- packed fp32x2 helpers (GRU matvec) ----
__device__ __forceinline__ u64 pk2(float lo, float hi) {
    u64 r; asm("mov.b64 %0, {%1, %2};" : "=l"(r) : "f"(lo), "f"(hi)); return r;
}
__device__ __forceinline__ u64 ffma2(u64 a, u64 b, u64 c) {
    u64 d; asm("fma.rn.f32x2 %0, %1, %2, %3;" : "=l"(d) : "l"(a), "l"(b), "l"(c)); return d;
}
__device__ __forceinline__ float pairsum(u64 v) {
    float x, y; asm("mov.b64 {%0, %1}, %2;" : "=f"(x), "=f"(y) : "l"(v)); return x + y;
}

__device__ __forceinline__ uint32_t tf32_of(float x) {
    uint32_t u; asm("cvt.rna.tf32.f32 %0, %1;" : "=r"(u) : "f"(x)); return u;
}
__device__ __forceinline__ void mma_tf32(float c[4], const uint32_t a[4], const uint32_t b[2]) {
    asm volatile(
        "mma.sync.aligned.m16n8k8.row.col.f32.tf32.tf32.f32 "
        "{%0,%1,%2,%3}, {%4,%5,%6,%7}, {%8,%9}, {%0,%1,%2,%3};"
        : "+f"(c[0]), "+f"(c[1]), "+f"(c[2]), "+f"(c[3])
        : "r"(a[0]), "r"(a[1]), "r"(a[2]), "r"(a[3]), "r"(b[0]), "r"(b[1]));
}

// ---------------- dep-type table ----------------
__global__ void prep_kernel(const float* __restrict__ D, const float* __restrict__ q) {
    __shared__ float qs[H];
    int t = blockIdx.x;
    if (threadIdx.x < H) qs[threadIdx.x] = q[t * H + threadIdx.x];
    __syncthreads();
    int j = threadIdx.x;
    const float* Drow = D + (size_t)j * H;
    float acc = 0.f;
#pragma unroll 8
    for (int k = 0; k < H; k++) acc += Drow[k] * qs[k];
    g_dq[t * NH3 + j] = acc;
}

// ---------------- wx via TF32 mma (R13) ----------------
__global__ __launch_bounds__(256) void wx_mma(
    const int* __restrict__ sidx, const int* __restrict__ dep,
    const float* __restrict__ idx2vec, const float* __restrict__ W,
    const float* __restrict__ bias) {
    __shared__ uint32_t As[128][36];
    __shared__ uint32_t Bs[64][36];
    __shared__ int   ridx[128];
    __shared__ int   djs[128];
    __shared__ float bsh[64];
    __shared__ float dqs[10][64];

    int tid = threadIdx.x;
    int wid = tid >> 5, lane = tid & 31;
    int warp_m = wid >> 1, warp_n = wid & 1;
    int lr = lane >> 2, lc = lane & 3;
    int n0 = blockIdx.x * 64, m0 = blockIdx.y * 128;

    if (tid < 128) {
        int m = m0 + tid;
        ridx[tid] = sidx[m];
        int s = m >> 6, l = m & 63;
        djs[tid] = (l == 63) ? 9 : dep[s * 63 + l];
    }
    if (tid < 64) bsh[tid] = bias[n0 + tid];
    for (int e = tid; e < 640; e += 256) {
        int t = e >> 6, c = e & 63;
        dqs[t][c] = g_dq[t * NH3 + n0 + c];
    }
    __syncthreads();

    float c[2][4][4];
#pragma unroll
    for (int mf = 0; mf < 2; mf++)
#pragma unroll
        for (int nf = 0; nf < 4; nf++)
#pragma unroll
            for (int r = 0; r < 4; r++) c[mf][nf][r] = 0.f;

    float4 av[4], bv[2];
    const float4 z4 = make_float4(0.f, 0.f, 0.f, 0.f);

#pragma unroll
    for (int i = 0; i < 4; i++) {
        int idx = tid + 256 * i;
        int m = idx >> 3, k4 = idx & 7;
        int off = k4 * 4;
        av[i] = (off < E) ? *(const float4*)(idx2vec + (size_t)ridx[m] * E + off) : z4;
    }
#pragma unroll
    for (int i = 0; i < 2; i++) {
        int idx = tid + 256 * i;
        int n = idx >> 3, k4 = idx & 7;
        int off = k4 * 4;
        bv[i] = (off < E) ? *(const float4*)(W + (size_t)(n0 + n) * E + off) : z4;
    }

    for (int it = 0; it < 10; it++) {
        __syncthreads();
#pragma unroll
        for (int i = 0; i < 4; i++) {
            int idx = tid + 256 * i;
            int m = idx >> 3, k4 = idx & 7;
            uint32_t* d = &As[m][k4 * 4];
            d[0] = tf32_of(av[i].x); d[1] = tf32_of(av[i].y);
            d[2] = tf32_of(av[i].z); d[3] = tf32_of(av[i].w);
        }
#pragma unroll
        for (int i = 0; i < 2; i++) {
            int idx = tid + 256 * i;
            int n = idx >> 3, k4 = idx & 7;
            uint32_t* d = &Bs[n][k4 * 4];
            d[0] = tf32_of(bv[i].x); d[1] = tf32_of(bv[i].y);
            d[2] = tf32_of(bv[i].z); d[3] = tf32_of(bv[i].w);
        }
        __syncthreads();
        if (it < 9) {
            int kbase = (it + 1) * 32;
#pragma unroll
            for (int i = 0; i < 4; i++) {
                int idx = tid + 256 * i;
                int m = idx >> 3, k4 = idx & 7;
                int off = kbase + k4 * 4;
                av[i] = (off < E) ? *(const float4*)(idx2vec + (size_t)ridx[m] * E + off) : z4;
            }
#pragma unroll
            for (int i = 0; i < 2; i++) {
                int idx = tid + 256 * i;
                int n = idx >> 3, k4 = idx & 7;
                int off = kbase + k4 * 4;
                bv[i] = (off < E) ? *(const float4*)(W + (size_t)(n0 + n) * E + off) : z4;
            }
        }
#pragma unroll
        for (int kf = 0; kf < 4; kf++) {
            int kcol = kf * 8 + lc;
            uint32_t a[2][4], bfr[4][2];
#pragma unroll
            for (int mf = 0; mf < 2; mf++) {
                int bm = warp_m * 32 + mf * 16 + lr;
                a[mf][0] = As[bm][kcol];
                a[mf][1] = As[bm + 8][kcol];
                a[mf][2] = As[bm][kcol + 4];
                a[mf][3] = As[bm + 8][kcol + 4];
            }
#pragma unroll
            for (int nf = 0; nf < 4; nf++) {
                int bn = warp_n * 32 + nf * 8 + lr;
                bfr[nf][0] = Bs[bn][kcol];
                bfr[nf][1] = Bs[bn][kcol + 4];
            }
#pragma unroll
            for (int mf = 0; mf < 2; mf++)
#pragma unroll
                for (int nf = 0; nf < 4; nf++)
                    mma_tf32(c[mf][nf], a[mf], bfr[nf]);
        }
    }

#pragma unroll
    for (int mf = 0; mf < 2; mf++) {
#pragma unroll
        for (int half = 0; half < 2; half++) {
            int ml = warp_m * 32 + mf * 16 + lr + half * 8;
            int m = m0 + ml;
            int s = m >> 6, l = m & 63;
            int dj = djs[ml];
            float* outr = ((l == 63) ? (g_leaf + (size_t)s * NH3)
                                     : (g_pre + (size_t)(s * 63 + l) * NH3)) + n0;
#pragma unroll
            for (int nf = 0; nf < 4; nf++) {
                int col = warp_n * 32 + nf * 8 + 2 * lc;
                float v0 = c[mf][nf][half * 2 + 0] + bsh[col] + dqs[dj][col];
                float v1 = c[mf][nf][half * 2 + 1] + bsh[col + 1] + dqs[dj][col + 1];
                *(float2*)(outr + col) = make_float2(v0, v1);
            }
        }
    }
}

// ---------------- leaf (writes ping buffer A) ----------------
__global__ void leaf_kernel() {
    int idx = blockIdx.x * 256 + threadIdx.x;
    int s = idx >> 8, i = idx & 255;
    const float* r = g_leaf + (size_t)s * NH3;
    g_hA[idx] = tanhf(sigf(r[256 + i]) * tanhf(r[512 + i]));
}

// ---------------- fused tree step, BM=32 for occupancy (grid 8 x 32) ----------------
__global__ __launch_bounds__(256) void tree_mma(const float* __restrict__ U, int k) {
    __shared__ uint32_t smb[4608];
    uint32_t (*As)[36] = (uint32_t(*)[36])smb;              // 32 x 36
    uint32_t (*Bs)[36] = (uint32_t(*)[36])(smb + 1152);     // 96 x 36
    float (*Cs)[100] = (float(*)[100])smb;                  // 32 x 100 (aliased)

    const float* hin = (k & 1) ? g_hB : g_hA;
    float* hout = (k & 1) ? g_hA : g_hB;

    int tid = threadIdx.x;
    int wid = tid >> 5, lane = tid & 31;
    int warp_m = wid >> 2, warp_n = wid & 3;    // 2 x 4
    int lr = lane >> 2, lc = lane & 3;
    int i0 = blockIdx.x * 32, m0 = blockIdx.y * 32;

    float c[3][4];
#pragma unroll
    for (int nf = 0; nf < 3; nf++)
#pragma unroll
        for (int r = 0; r < 4; r++) c[nf][r] = 0.f;

    float4 av, bv[3];
    // prologue: k-tile 0
    {
        int ml = tid >> 3, k4 = tid & 7;
        av = *(const float4*)(hin + (size_t)(m0 + ml) * H + k4 * 4);
    }
#pragma unroll
    for (int i = 0; i < 3; i++) {
        int idx = tid + 256 * i;
        int bl = idx >> 3, k4 = idx & 7;
        int g = bl >> 5, r = bl & 31;
        bv[i] = *(const float4*)(U + (size_t)(g * H + i0 + r) * H + k4 * 4);
    }

    for (int it = 0; it < 8; it++) {
        __syncthreads();
        {
            int ml = tid >> 3, k4 = tid & 7;
            uint32_t* d = &As[ml][k4 * 4];
            d[0] = tf32_of(av.x); d[1] = tf32_of(av.y);
            d[2] = tf32_of(av.z); d[3] = tf32_of(av.w);
        }
#pragma unroll
        for (int i = 0; i < 3; i++) {
            int idx = tid + 256 * i;
            int bl = idx >> 3, k4 = idx & 7;
            uint32_t* d = &Bs[bl][k4 * 4];
            d[0] = tf32_of(bv[i].x); d[1] = tf32_of(bv[i].y);
            d[2] = tf32_of(bv[i].z); d[3] = tf32_of(bv[i].w);
        }
        __syncthreads();
        if (it < 7) {
            int kbase = (it + 1) * 32;
            {
                int ml = tid >> 3, k4 = tid & 7;
                av = *(const float4*)(hin + (size_t)(m0 + ml) * H + kbase + k4 * 4);
            }
#pragma unroll
            for (int i = 0; i < 3; i++) {
                int idx = tid + 256 * i;
                int bl = idx >> 3, k4 = idx & 7;
                int g = bl >> 5, r = bl & 31;
                bv[i] = *(const float4*)(U + (size_t)(g * H + i0 + r) * H + kbase + k4 * 4);
            }
        }
#pragma unroll
        for (int kf = 0; kf < 4; kf++) {
            int kcol = kf * 8 + lc;
            uint32_t a[4], bfr[3][2];
            int bm = warp_m * 16 + lr;
            a[0] = As[bm][kcol];
            a[1] = As[bm + 8][kcol];
            a[2] = As[bm][kcol + 4];
            a[3] = As[bm + 8][kcol + 4];
#pragma unroll
            for (int nf = 0; nf < 3; nf++) {
                int bn = warp_n * 24 + nf * 8 + lr;
                bfr[nf][0] = Bs[bn][kcol];
                bfr[nf][1] = Bs[bn][kcol + 4];
            }
#pragma unroll
            for (int nf = 0; nf < 3; nf++)
                mma_tf32(c[nf], a, bfr[nf]);
        }
    }

    // stage C into smem (aliases As/Bs — mma reads done)
    __syncthreads();
    {
        int r0 = warp_m * 16 + lr;
#pragma unroll
        for (int nf = 0; nf < 3; nf++) {
            int colw = warp_n * 24 + nf * 8 + 2 * lc;
            Cs[r0][colw]     = c[nf][0];
            Cs[r0][colw + 1] = c[nf][1];
            Cs[r0 + 8][colw]     = c[nf][2];
            Cs[r0 + 8][colw + 1] = c[nf][3];
        }
    }
    __syncthreads();

    // elem update for this (s, i) block: 32 x 32
    for (int e = tid; e < 32 * 32; e += 256) {
        int ml = e >> 5, ii = e & 31;
        int s = m0 + ml, ig = i0 + ii;
        size_t pb = ((size_t)s * 63 + k) * NH3;
        float t0 = Cs[ml][ii]      + g_pre[pb + ig];
        float t1 = Cs[ml][32 + ii] + g_pre[pb + 256 + ig];
        float t2 = Cs[ml][64 + ii] + g_pre[pb + 512 + ig];
        float hc = hin[(size_t)s * H + ig];
        hout[(size_t)s * H + ig] = tanhf(sigf(t1) * tanhf(t2) + sigf(t0) * hc);
    }
}

// ---------------- gi GEMM (R12 kernel, reads g_hB) ----------------
__global__ __launch_bounds__(256) void ab_mma(const float* __restrict__ B) {
    __shared__ uint32_t As[128][36];
    __shared__ uint32_t Bs[64][36];

    int tid = threadIdx.x;
    int wid = tid >> 5, lane = tid & 31;
    int warp_m = wid >> 1, warp_n = wid & 1;
    int lr = lane >> 2, lc = lane & 3;
    int n0 = blockIdx.x * 64, m0 = blockIdx.y * 128, kb = blockIdx.z * 128;

    float c[2][4][4];
#pragma unroll
    for (int mf = 0; mf < 2; mf++)
#pragma unroll
        for (int nf = 0; nf < 4; nf++)
#pragma unroll
            for (int r = 0; r < 4; r++) c[mf][nf][r] = 0.f;

    for (int it = 0; it < 4; it++) {
        int kbase = kb + it * 32;
        float4 av[4], bv[2];
#pragma unroll
        for (int i = 0; i < 4; i++) {
            int idx = tid + 256 * i;
            int m = idx >> 3, k4 = idx & 7;
            av[i] = *(const float4*)(g_hB + (size_t)(m0 + m) * H + kbase + k4 * 4);
        }
#pragma unroll
        for (int i = 0; i < 2; i++) {
            int idx = tid + 256 * i;
            int n = idx >> 3, k4 = idx & 7;
            bv[i] = *(const float4*)(B + (size_t)(n0 + n) * H + kbase + k4 * 4);
        }
        __syncthreads();
#pragma unroll
        for (int i = 0; i < 4; i++) {
            int idx = tid + 256 * i;
            int m = idx >> 3, k4 = idx & 7;
            uint32_t* d = &As[m][k4 * 4];
            d[0] = tf32_of(av[i].x); d[1] = tf32_of(av[i].y);
            d[2] = tf32_of(av[i].z); d[3] = tf32_of(av[i].w);
        }
#pragma unroll
        for (int i = 0; i < 2; i++) {
            int idx = tid + 256 * i;
            int n = idx >> 3, k4 = idx & 7;
            uint32_t* d = &Bs[n][k4 * 4];
            d[0] = tf32_of(bv[i].x); d[1] = tf32_of(bv[i].y);
            d[2] = tf32_of(bv[i].z); d[3] = tf32_of(bv[i].w);
        }
        __syncthreads();
#pragma unroll
        for (int kf = 0; kf < 4; kf++) {
            int kcol = kf * 8 + lc;
            uint32_t a[2][4], bfr[4][2];
#pragma unroll
            for (int mf = 0; mf < 2; mf++) {
                int bm = warp_m * 32 + mf * 16 + lr;
                a[mf][0] = As[bm][kcol];
                a[mf][1] = As[bm + 8][kcol];
                a[mf][2] = As[bm][kcol + 4];
                a[mf][3] = As[bm + 8][kcol + 4];
            }
#pragma unroll
            for (int nf = 0; nf < 4; nf++) {
                int bn = warp_n * 32 + nf * 8 + lr;
                bfr[nf][0] = Bs[bn][kcol];
                bfr[nf][1] = Bs[bn][kcol + 4];
            }
#pragma unroll
            for (int mf = 0; mf < 2; mf++)
#pragma unroll
                for (int nf = 0; nf < 4; nf++)
                    mma_tf32(c[mf][nf], a[mf], bfr[nf]);
        }
    }

    float* Cw = blockIdx.z ? g_pB : g_pA;
#pragma unroll
    for (int mf = 0; mf < 2; mf++) {
        int r0 = m0 + warp_m * 32 + mf * 16 + lr;
#pragma unroll
        for (int nf = 0; nf < 4; nf++) {
            int col = n0 + warp_n * 32 + nf * 8 + 2 * lc;
            *(float2*)(Cw + (size_t)r0 * NH3 + col) = make_float2(c[mf][nf][0], c[mf][nf][1]);
            *(float2*)(Cw + (size_t)(r0 + 8) * NH3 + col) = make_float2(c[mf][nf][2], c[mf][nf][3]);
        }
    }
}

// ---------------- gi = partials + bih ----------------
__global__ void gi_combine_kernel(const float* __restrict__ bih) {
    int idx = blockIdx.x * 256 + threadIdx.x;
    int n = idx % NH3;
    g_gi[idx] = g_pA[idx] + g_pB[idx] + bih[n];
}

// ---------------- GRU: 8-CTA cluster, R7 pull protocol + gi prefetch ----------------
__device__ __forceinline__ uint32_t smem_u32(const void* p) {
    return (uint32_t)__cvta_generic_to_shared(p);
}
__device__ __forceinline__ uint32_t mapa_u32(uint32_t a, uint32_t r) {
    uint32_t o;
    asm("mapa.shared::cluster.u32 %0, %1, %2;" : "=r"(o) : "r"(a), "r"(r));
    return o;
}
__device__ __forceinline__ float ld_remote(uint32_t a) {
    float v;
    asm volatile("ld.shared::cluster.f32 %0, [%1];" : "=f"(v) : "r"(a) : "memory");
    return v;
}
__device__ __forceinline__ void cluster_barrier() {
    asm volatile("barrier.cluster.arrive.aligned;" ::: "memory");
    asm volatile("barrier.cluster.wait.aligned;" ::: "memory");
}

__global__ void __cluster_dims__(8, 1, 1) __launch_bounds__(256, 1)
gru_kernel(const float* __restrict__ whh, const float* __restrict__ bhh,
           const float* __restrict__ h0) {
    __shared__ __align__(16) float hsh[H];
    __shared__ float ghsh[2][96];

    int tid = threadIdx.x;
    unsigned rank;
    asm("mov.u32 %0, %%cluster_ctarank;" : "=r"(rank));
    int g = tid >> 3, p = tid & 7;
    int jbase = (int)rank * 96 + g * 3;

    u64 wp[3][16];
    float bh[3];
#pragma unroll
    for (int c = 0; c < 3; c++) {
        int j = jbase + c;
        bh[c] = bhh[j];
        const float4* wr = (const float4*)(whh + (size_t)j * H + p * 32);
#pragma unroll
        for (int u = 0; u < 8; u++) {
            float4 v = wr[u];
            wp[c][2 * u]     = pk2(v.x, v.y);
            wp[c][2 * u + 1] = pk2(v.z, v.w);
        }
    }
    hsh[tid] = h0[tid];

    uint32_t radr[2][3];
#pragma unroll
    for (int par = 0; par < 2; par++)
#pragma unroll
        for (int c = 0; c < 3; c++) {
            int j = c * H + tid;
            radr[par][c] = mapa_u32(smem_u32(&ghsh[par][j % 96]), (uint32_t)(j / 96));
        }

    // gi prologue: step 0 loads
    float gi0 = __ldg(g_gi + tid), gi1 = __ldg(g_gi + 256 + tid), gi2 = __ldg(g_gi + 512 + tid);

    for (int t = 0; t < S_SENT; t++) {
        __syncthreads();
        int par = t & 1;

        u64 hvp[16];
        const float4* hp = (const float4*)(hsh + p * 32);
#pragma unroll
        for (int u = 0; u < 8; u++) {
            float4 v = hp[u];
            hvp[2 * u]     = pk2(v.x, v.y);
            hvp[2 * u + 1] = pk2(v.z, v.w);
        }
        u64 pa0 = 0ull, pa1 = 0ull, pa2 = 0ull;
#pragma unroll
        for (int u = 0; u < 16; u++) {
            pa0 = ffma2(wp[0][u], hvp[u], pa0);
            pa1 = ffma2(wp[1][u], hvp[u], pa1);
            pa2 = ffma2(wp[2][u], hvp[u], pa2);
        }
        float a0 = pairsum(pa0), a1 = pairsum(pa1), a2 = pairsum(pa2);
#pragma unroll
        for (int off = 4; off > 0; off >>= 1) {
            a0 += __shfl_down_sync(0xffffffffu, a0, off, 8);
            a1 += __shfl_down_sync(0xffffffffu, a1, off, 8);
            a2 += __shfl_down_sync(0xffffffffu, a2, off, 8);
        }
        if (p == 0) {
            ghsh[par][g * 3 + 0] = a0 + bh[0];
            ghsh[par][g * 3 + 1] = a1 + bh[1];
            ghsh[par][g * 3 + 2] = a2 + bh[2];
        }
        // prefetch next step's gi (latency hides behind the barrier)
        float ngi0 = 0.f, ngi1 = 0.f, ngi2 = 0.f;
        if (t + 1 < S_SENT) {
            const float* gnr = g_gi + (size_t)(t + 1) * NH3;
            ngi0 = __ldg(gnr + tid); ngi1 = __ldg(gnr + 256 + tid); ngi2 = __ldg(gnr + 512 + tid);
        }
        cluster_barrier();

        float gh0 = ld_remote(radr[par][0]);
        float gh1 = ld_remote(radr[par][1]);
        float gh2 = ld_remote(radr[par][2]);
        float hh = hsh[tid];
        float r = sigf(gi0 + gh0);
        float z = sigf(gi1 + gh1);
        float n = tanhf(gi2 + r * gh2);
        hsh[tid] = (1.0f - z) * n + z * hh;

        gi0 = ngi0; gi1 = ngi1; gi2 = ngi2;
    }
    __syncthreads();
    if (rank == 0) g_hT[tid] = hsh[tid];
}

// ---------------- final: topic, gate, classifier, softmax ----------------
__global__ void final_kernel(const float* __restrict__ DT,
                             const float* __restrict__ gate_W, const float* __restrict__ gate_U,
                             const float* __restrict__ gate_b,
                             const float* __restrict__ mlp_W, const float* __restrict__ mlp_b,
                             const float* __restrict__ out_W, const float* __restrict__ out_b,
                             float* __restrict__ out) {
    __shared__ float tsh[H], hsh[H], vsh[H], lg[NTGT];
    int tid = threadIdx.x;
    float acc = mlp_b[tid];
    const float* mr = mlp_W + (size_t)tid * NTOPIC;
#pragma unroll 4
    for (int k = 0; k < NTOPIC; k++) acc += mr[k] * DT[k];
    tsh[tid] = tanhf(acc);
    hsh[tid] = g_hT[tid];
    __syncthreads();
    float ga = gate_b[tid], gb = gate_b[tid + H];
    const float* wr = gate_W + (size_t)tid * H;
    const float* wr2 = gate_W + (size_t)(tid + H) * H;
    const float* ur = gate_U + (size_t)tid * H;
    const float* ur2 = gate_U + (size_t)(tid + H) * H;
#pragma unroll 4
    for (int k = 0; k < H; k++) {
        float hk = hsh[k], tk = tsh[k];
        ga += wr[k] * hk + ur[k] * tk;
        gb += wr2[k] * hk + ur2[k] * tk;
    }
    vsh[tid] = tanhf(sigf(ga) * hsh[tid] + sigf(gb) * tsh[tid]);
    __syncthreads();
    int wix = tid >> 5, lane = tid & 31;
    if (wix < NTGT) {
        float a = 0.f;
        for (int k = lane; k < H; k += 32) a += out_W[wix * H + k] * vsh[k];
#pragma unroll
        for (int off = 16; off > 0; off >>= 1) a += __shfl_down_sync(0xffffffffu, a, off);
        if (lane == 0) lg[wix] = a + out_b[wix];
    }
    __syncthreads();
    if (tid == 0) {
        float mx = lg[0];
        for (int i = 1; i < NTGT; i++) mx = fmaxf(mx, lg[i]);
        float s = 0.f, e[NTGT];
        for (int i = 0; i < NTGT; i++) { e[i] = expf(lg[i] - mx); s += e[i]; }
        for (int i = 0; i < NTGT; i++) out[i] = e[i] / s;
    }
}

extern "C" void kernel_launch(void* const* d_in, const int* in_sizes, int n_in,
                              void* d_out, int out_size) {
    const int*   sidx    = (const int*)  d_in[0];
    const int*   dep     = (const int*)  d_in[1];
    const float* DT      = (const float*)d_in[2];
    const float* h0      = (const float*)d_in[3];
    const float* idx2vec = (const float*)d_in[4];
    const float* q       = (const float*)d_in[5];
    const float* W       = (const float*)d_in[6];
    const float* U       = (const float*)d_in[7];
    const float* D       = (const float*)d_in[8];
    const float* b       = (const float*)d_in[9];
    const float* gru_wih = (const float*)d_in[10];
    const float* gru_whh = (const float*)d_in[11];
    const float* gru_bih = (const float*)d_in[12];
    const float* gru_bhh = (const float*)d_in[13];
    const float* gate_W  = (const float*)d_in[14];
    const float* gate_U  = (const float*)d_in[15];
    const float* gate_b  = (const float*)d_in[16];
    const float* mlp_W   = (const float*)d_in[17];
    const float* mlp_b   = (const float*)d_in[18];
    const float* out_W   = (const float*)d_in[19];
    const float* out_b   = (const float*)d_in[20];
    float* out = (float*)d_out;

    prep_kernel<<<10, NH3>>>(D, q);
    wx_mma<<<dim3(12, 512), 256>>>(sidx, dep, idx2vec, W, b);
    leaf_kernel<<<1024, 256>>>();

    for (int k = L_W - 2; k >= 0; k--)
        tree_mma<<<dim3(8, 32), 256>>>(U, k);

    ab_mma<<<dim3(12, 8, 2), 256>>>(gru_wih);
    gi_combine_kernel<<<3072, 256>>>(gru_bih);

    gru_kernel<<<8, 256>>>(gru_whh, gru_bhh, h0);

    final_kernel<<<1, 256>>>(DT, gate_W, gate_U, gate_b, mlp_W, mlp_b, out_W, out_b, out);
}

// round 17
// speedup vs baseline: 1.4482x; 1.0044x over previous
#include <cuda_runtime.h>
#include <cuda_bf16.h>
#include <cstdint>
#include <math.h>

#define H      256
#define E      300
#define S_SENT 1024
#define L_W    64
#define NH3    768
#define NTOPIC 100
#define NTGT   5

typedef unsigned long long u64;

// ---------------- scratch ----------------
__device__ float g_dq[10 * NH3];
__device__ float g_pre[S_SENT * (L_W - 1) * NH3];
__device__ float g_leaf[S_SENT * NH3];
__device__ float g_hA[S_SENT * H];
__device__ float g_hB[S_SENT * H];
__device__ float g_pA[S_SENT * NH3];
__device__ float g_pB[S_SENT * NH3];
__device__ float g_gi[S_SENT * NH3];
__device__ float g_hT[H];

__device__ __forceinline__ float sigf(float x) { return 1.0f / (1.0f + expf(-x)); }

// ---- packed fp32x2 helpers (GRU matvec) ----
__device__ __forceinline__ u64 pk2(float lo, float hi) {
    u64 r; asm("mov.b64 %0, {%1, %2};" : "=l"(r) : "f"(lo), "f"(hi)); return r;
}
__device__ __forceinline__ u64 ffma2(u64 a, u64 b, u64 c) {
    u64 d; asm("fma.rn.f32x2 %0, %1, %2, %3;" : "=l"(d) : "l"(a), "l"(b), "l"(c)); return d;
}
__device__ __forceinline__ float pairsum(u64 v) {
    float x, y; asm("mov.b64 {%0, %1}, %2;" : "=f"(x), "=f"(y) : "l"(v)); return x + y;
}

__device__ __forceinline__ uint32_t tf32_of(float x) {
    uint32_t u; asm("cvt.rna.tf32.f32 %0, %1;" : "=r"(u) : "f"(x)); return u;
}
__device__ __forceinline__ void mma_tf32(float c[4], const uint32_t a[4], const uint32_t b[2]) {
    asm volatile(
        "mma.sync.aligned.m16n8k8.row.col.f32.tf32.tf32.f32 "
        "{%0,%1,%2,%3}, {%4,%5,%6,%7}, {%8,%9}, {%0,%1,%2,%3};"
        : "+f"(c[0]), "+f"(c[1]), "+f"(c[2]), "+f"(c[3])
        : "r"(a[0]), "r"(a[1]), "r"(a[2]), "r"(a[3]), "r"(b[0]), "r"(b[1]));
}

__device__ __forceinline__ uint32_t smem_u32(const void* p) {
    return (uint32_t)__cvta_generic_to_shared(p);
}
__device__ __forceinline__ uint32_t mapa_u32(uint32_t a, uint32_t r) {
    uint32_t o;
    asm("mapa.shared::cluster.u32 %0, %1, %2;" : "=r"(o) : "r"(a), "r"(r));
    return o;
}
__device__ __forceinline__ float ld_remote(uint32_t a) {
    float v;
    asm volatile("ld.shared::cluster.f32 %0, [%1];" : "=f"(v) : "r"(a) : "memory");
    return v;
}
__device__ __forceinline__ void cluster_barrier() {
    asm volatile("barrier.cluster.arrive.aligned;" ::: "memory");
    asm volatile("barrier.cluster.wait.aligned;" ::: "memory");
}

// ---------------- dep-type table ----------------
__global__ void prep_kernel(const float* __restrict__ D, const float* __restrict__ q) {
    __shared__ float qs[H];
    int t = blockIdx.x;
    if (threadIdx.x < H) qs[threadIdx.x] = q[t * H + threadIdx.x];
    __syncthreads();
    int j = threadIdx.x;
    const float* Drow = D + (size_t)j * H;
    float acc = 0.f;
#pragma unroll 8
    for (int k = 0; k < H; k++) acc += Drow[k] * qs[k];
    g_dq[t * NH3 + j] = acc;
}

// ---------------- wx via TF32 mma ----------------
__global__ __launch_bounds__(256) void wx_mma(
    const int* __restrict__ sidx, const int* __restrict__ dep,
    const float* __restrict__ idx2vec, const float* __restrict__ W,
    const float* __restrict__ bias) {
    __shared__ uint32_t As[128][36];
    __shared__ uint32_t Bs[64][36];
    __shared__ int   ridx[128];
    __shared__ int   djs[128];
    __shared__ float bsh[64];
    __shared__ float dqs[10][64];

    int tid = threadIdx.x;
    int wid = tid >> 5, lane = tid & 31;
    int warp_m = wid >> 1, warp_n = wid & 1;
    int lr = lane >> 2, lc = lane & 3;
    int n0 = blockIdx.x * 64, m0 = blockIdx.y * 128;

    if (tid < 128) {
        int m = m0 + tid;
        ridx[tid] = sidx[m];
        int s = m >> 6, l = m & 63;
        djs[tid] = (l == 63) ? 9 : dep[s * 63 + l];
    }
    if (tid < 64) bsh[tid] = bias[n0 + tid];
    for (int e = tid; e < 640; e += 256) {
        int t = e >> 6, c = e & 63;
        dqs[t][c] = g_dq[t * NH3 + n0 + c];
    }
    __syncthreads();

    float c[2][4][4];
#pragma unroll
    for (int mf = 0; mf < 2; mf++)
#pragma unroll
        for (int nf = 0; nf < 4; nf++)
#pragma unroll
            for (int r = 0; r < 4; r++) c[mf][nf][r] = 0.f;

    float4 av[4], bv[2];
    const float4 z4 = make_float4(0.f, 0.f, 0.f, 0.f);

#pragma unroll
    for (int i = 0; i < 4; i++) {
        int idx = tid + 256 * i;
        int m = idx >> 3, k4 = idx & 7;
        int off = k4 * 4;
        av[i] = (off < E) ? *(const float4*)(idx2vec + (size_t)ridx[m] * E + off) : z4;
    }
#pragma unroll
    for (int i = 0; i < 2; i++) {
        int idx = tid + 256 * i;
        int n = idx >> 3, k4 = idx & 7;
        int off = k4 * 4;
        bv[i] = (off < E) ? *(const float4*)(W + (size_t)(n0 + n) * E + off) : z4;
    }

    for (int it = 0; it < 10; it++) {
        __syncthreads();
#pragma unroll
        for (int i = 0; i < 4; i++) {
            int idx = tid + 256 * i;
            int m = idx >> 3, k4 = idx & 7;
            uint32_t* d = &As[m][k4 * 4];
            d[0] = tf32_of(av[i].x); d[1] = tf32_of(av[i].y);
            d[2] = tf32_of(av[i].z); d[3] = tf32_of(av[i].w);
        }
#pragma unroll
        for (int i = 0; i < 2; i++) {
            int idx = tid + 256 * i;
            int n = idx >> 3, k4 = idx & 7;
            uint32_t* d = &Bs[n][k4 * 4];
            d[0] = tf32_of(bv[i].x); d[1] = tf32_of(bv[i].y);
            d[2] = tf32_of(bv[i].z); d[3] = tf32_of(bv[i].w);
        }
        __syncthreads();
        if (it < 9) {
            int kbase = (it + 1) * 32;
#pragma unroll
            for (int i = 0; i < 4; i++) {
                int idx = tid + 256 * i;
                int m = idx >> 3, k4 = idx & 7;
                int off = kbase + k4 * 4;
                av[i] = (off < E) ? *(const float4*)(idx2vec + (size_t)ridx[m] * E + off) : z4;
            }
#pragma unroll
            for (int i = 0; i < 2; i++) {
                int idx = tid + 256 * i;
                int n = idx >> 3, k4 = idx & 7;
                int off = kbase + k4 * 4;
                bv[i] = (off < E) ? *(const float4*)(W + (size_t)(n0 + n) * E + off) : z4;
            }
        }
#pragma unroll
        for (int kf = 0; kf < 4; kf++) {
            int kcol = kf * 8 + lc;
            uint32_t a[2][4], bfr[4][2];
#pragma unroll
            for (int mf = 0; mf < 2; mf++) {
                int bm = warp_m * 32 + mf * 16 + lr;
                a[mf][0] = As[bm][kcol];
                a[mf][1] = As[bm + 8][kcol];
                a[mf][2] = As[bm][kcol + 4];
                a[mf][3] = As[bm + 8][kcol + 4];
            }
#pragma unroll
            for (int nf = 0; nf < 4; nf++) {
                int bn = warp_n * 32 + nf * 8 + lr;
                bfr[nf][0] = Bs[bn][kcol];
                bfr[nf][1] = Bs[bn][kcol + 4];
            }
#pragma unroll
            for (int mf = 0; mf < 2; mf++)
#pragma unroll
                for (int nf = 0; nf < 4; nf++)
                    mma_tf32(c[mf][nf], a[mf], bfr[nf]);
        }
    }

#pragma unroll
    for (int mf = 0; mf < 2; mf++) {
#pragma unroll
        for (int half = 0; half < 2; half++) {
            int ml = warp_m * 32 + mf * 16 + lr + half * 8;
            int m = m0 + ml;
            int s = m >> 6, l = m & 63;
            int dj = djs[ml];
            float* outr = ((l == 63) ? (g_leaf + (size_t)s * NH3)
                                     : (g_pre + (size_t)(s * 63 + l) * NH3)) + n0;
#pragma unroll
            for (int nf = 0; nf < 4; nf++) {
                int col = warp_n * 32 + nf * 8 + 2 * lc;
                float v0 = c[mf][nf][half * 2 + 0] + bsh[col] + dqs[dj][col];
                float v1 = c[mf][nf][half * 2 + 1] + bsh[col + 1] + dqs[dj][col + 1];
                *(float2*)(outr + col) = make_float2(v0, v1);
            }
        }
    }
}

// ---------------- leaf (writes ping buffer A) ----------------
__global__ void leaf_kernel() {
    int idx = blockIdx.x * 256 + threadIdx.x;
    int s = idx >> 8, i = idx & 255;
    const float* r = g_leaf + (size_t)s * NH3;
    g_hA[idx] = tanhf(sigf(r[256 + i]) * tanhf(r[512 + i]));
}

// ---------------- persistent tree: 16 clusters x 8 CTAs, U resident in smem ----------------
// Each CTA: 96 U-rows = its own (3 gates x 32 i-cols) for 64 sentences.
// mma 64x96x256 per step; h exchanged via gmem ping-pong + barrier.cluster.
#define USTRIDE 260
#define TREE_SMEM ((96 * USTRIDE + 64 * USTRIDE) * 4)

__global__ void __cluster_dims__(8, 1, 1) __launch_bounds__(256, 1)
tree_persist(const float* __restrict__ U) {
    extern __shared__ uint32_t tsm[];
    uint32_t* Us = tsm;                       // [96][USTRIDE]
    uint32_t* As = tsm + 96 * USTRIDE;        // [64][USTRIDE]
    float (*Cs)[100] = (float(*)[100])As;     // aliased after mma

    int tid = threadIdx.x;
    unsigned rank;
    asm("mov.u32 %0, %%cluster_ctarank;" : "=r"(rank));
    int s0 = (blockIdx.x >> 3) * 64;
    int i0 = (int)rank * 32;

    int wid = tid >> 5, lane = tid & 31;
    int warp_m = wid >> 1, warp_n = wid & 1;   // 4(m) x 2(n)
    int lr = lane >> 2, lc = lane & 3;

    // one-time: U rows g*256 + i0 + r (g in 0..2, r in 0..31), tf32 in smem
    for (int idx = tid; idx < 96 * 64; idx += 256) {
        int row = idx >> 6, c4 = idx & 63;
        int g = row >> 5, r = row & 31;
        float4 v = *(const float4*)(U + (size_t)(g * H + i0 + r) * H + c4 * 4);
        uint32_t* d = &Us[row * USTRIDE + c4 * 4];
        d[0] = tf32_of(v.x); d[1] = tf32_of(v.y);
        d[2] = tf32_of(v.z); d[3] = tf32_of(v.w);
    }

    for (int k = 62; k >= 0; k--) {
        const float* hin  = (k & 1) ? g_hB : g_hA;
        float*       hout = (k & 1) ? g_hA : g_hB;

        // stage A: 64 sentences x 256 floats = 4096 float4 (64 float4 per row)
#pragma unroll
        for (int i = 0; i < 16; i++) {
            int idx = tid + 256 * i;
            int s = idx >> 6, c4 = idx & 63;
            float4 v = *(const float4*)(hin + (size_t)(s0 + s) * H + c4 * 4);
            uint32_t* d = &As[s * USTRIDE + c4 * 4];
            d[0] = tf32_of(v.x); d[1] = tf32_of(v.y);
            d[2] = tf32_of(v.z); d[3] = tf32_of(v.w);
        }
        // prefetch pre + exact h (for the f-gate product)
        float pr0[8], pr1[8], pr2[8], hcv[8];
#pragma unroll
        for (int r = 0; r < 8; r++) {
            int e = tid + 256 * r;
            int ml = e >> 5, ii = e & 31;
            size_t pb = ((size_t)(s0 + ml) * 63 + k) * NH3;
            pr0[r] = g_pre[pb + i0 + ii];
            pr1[r] = g_pre[pb + 256 + i0 + ii];
            pr2[r] = g_pre[pb + 512 + i0 + ii];
            hcv[r] = hin[(size_t)(s0 + ml) * H + i0 + ii];
        }
        __syncthreads();       // A (and, first iter, Us) visible

        float c[6][4];
#pragma unroll
        for (int nf = 0; nf < 6; nf++)
#pragma unroll
            for (int r = 0; r < 4; r++) c[nf][r] = 0.f;

#pragma unroll 4
        for (int kf = 0; kf < 32; kf++) {
            int kcol = kf * 8 + lc;
            uint32_t a[4], bfr[6][2];
            int bm = warp_m * 16 + lr;
            a[0] = As[bm * USTRIDE + kcol];
            a[1] = As[(bm + 8) * USTRIDE + kcol];
            a[2] = As[bm * USTRIDE + kcol + 4];
            a[3] = As[(bm + 8) * USTRIDE + kcol + 4];
#pragma unroll
            for (int nf = 0; nf < 6; nf++) {
                int bn = warp_n * 48 + nf * 8 + lr;
                bfr[nf][0] = Us[bn * USTRIDE + kcol];
                bfr[nf][1] = Us[bn * USTRIDE + kcol + 4];
            }
#pragma unroll
            for (int nf = 0; nf < 6; nf++)
                mma_tf32(c[nf], a, bfr[nf]);
        }
        __syncthreads();       // mma reads of As done; safe to alias as Cs

        {
            int r0 = warp_m * 16 + lr;
#pragma unroll
            for (int nf = 0; nf < 6; nf++) {
                int colw = warp_n * 48 + nf * 8 + 2 * lc;
                *(float2*)&Cs[r0][colw]     = make_float2(c[nf][0], c[nf][1]);
                *(float2*)&Cs[r0 + 8][colw] = make_float2(c[nf][2], c[nf][3]);
            }
        }
        __syncthreads();

        // elem update for own (s, i) block: 64 x 32
#pragma unroll
        for (int r = 0; r < 8; r++) {
            int e = tid + 256 * r;
            int ml = e >> 5, ii = e & 31;
            float t0 = Cs[ml][ii]      + pr0[r];
            float t1 = Cs[ml][32 + ii] + pr1[r];
            float t2 = Cs[ml][64 + ii] + pr2[r];
            hout[(size_t)(s0 + ml) * H + i0 + ii] =
                tanhf(sigf(t1) * tanhf(t2) + sigf(t0) * hcv[r]);
        }
        cluster_barrier();     // release hout; acquire for next step's hin
    }
}

// ---------------- gi GEMM (reads g_hB) ----------------
__global__ __launch_bounds__(256) void ab_mma(const float* __restrict__ B) {
    __shared__ uint32_t As[128][36];
    __shared__ uint32_t Bs[64][36];

    int tid = threadIdx.x;
    int wid = tid >> 5, lane = tid & 31;
    int warp_m = wid >> 1, warp_n = wid & 1;
    int lr = lane >> 2, lc = lane & 3;
    int n0 = blockIdx.x * 64, m0 = blockIdx.y * 128, kb = blockIdx.z * 128;

    float c[2][4][4];
#pragma unroll
    for (int mf = 0; mf < 2; mf++)
#pragma unroll
        for (int nf = 0; nf < 4; nf++)
#pragma unroll
            for (int r = 0; r < 4; r++) c[mf][nf][r] = 0.f;

    for (int it = 0; it < 4; it++) {
        int kbase = kb + it * 32;
        float4 av[4], bv[2];
#pragma unroll
        for (int i = 0; i < 4; i++) {
            int idx = tid + 256 * i;
            int m = idx >> 3, k4 = idx & 7;
            av[i] = *(const float4*)(g_hB + (size_t)(m0 + m) * H + kbase + k4 * 4);
        }
#pragma unroll
        for (int i = 0; i < 2; i++) {
            int idx = tid + 256 * i;
            int n = idx >> 3, k4 = idx & 7;
            bv[i] = *(const float4*)(B + (size_t)(n0 + n) * H + kbase + k4 * 4);
        }
        __syncthreads();
#pragma unroll
        for (int i = 0; i < 4; i++) {
            int idx = tid + 256 * i;
            int m = idx >> 3, k4 = idx & 7;
            uint32_t* d = &As[m][k4 * 4];
            d[0] = tf32_of(av[i].x); d[1] = tf32_of(av[i].y);
            d[2] = tf32_of(av[i].z); d[3] = tf32_of(av[i].w);
        }
#pragma unroll
        for (int i = 0; i < 2; i++) {
            int idx = tid + 256 * i;
            int n = idx >> 3, k4 = idx & 7;
            uint32_t* d = &Bs[n][k4 * 4];
            d[0] = tf32_of(bv[i].x); d[1] = tf32_of(bv[i].y);
            d[2] = tf32_of(bv[i].z); d[3] = tf32_of(bv[i].w);
        }
        __syncthreads();
#pragma unroll
        for (int kf = 0; kf < 4; kf++) {
            int kcol = kf * 8 + lc;
            uint32_t a[2][4], bfr[4][2];
#pragma unroll
            for (int mf = 0; mf < 2; mf++) {
                int bm = warp_m * 32 + mf * 16 + lr;
                a[mf][0] = As[bm][kcol];
                a[mf][1] = As[bm + 8][kcol];
                a[mf][2] = As[bm][kcol + 4];
                a[mf][3] = As[bm + 8][kcol + 4];
            }
#pragma unroll
            for (int nf = 0; nf < 4; nf++) {
                int bn = warp_n * 32 + nf * 8 + lr;
                bfr[nf][0] = Bs[bn][kcol];
                bfr[nf][1] = Bs[bn][kcol + 4];
            }
#pragma unroll
            for (int mf = 0; mf < 2; mf++)
#pragma unroll
                for (int nf = 0; nf < 4; nf++)
                    mma_tf32(c[mf][nf], a[mf], bfr[nf]);
        }
    }

    float* Cw = blockIdx.z ? g_pB : g_pA;
#pragma unroll
    for (int mf = 0; mf < 2; mf++) {
        int r0 = m0 + warp_m * 32 + mf * 16 + lr;
#pragma unroll
        for (int nf = 0; nf < 4; nf++) {
            int col = n0 + warp_n * 32 + nf * 8 + 2 * lc;
            *(float2*)(Cw + (size_t)r0 * NH3 + col) = make_float2(c[mf][nf][0], c[mf][nf][1]);
            *(float2*)(Cw + (size_t)(r0 + 8) * NH3 + col) = make_float2(c[mf][nf][2], c[mf][nf][3]);
        }
    }
}

// ---------------- gi = partials + bih ----------------
__global__ void gi_combine_kernel(const float* __restrict__ bih) {
    int idx = blockIdx.x * 256 + threadIdx.x;
    int n = idx % NH3;
    g_gi[idx] = g_pA[idx] + g_pB[idx] + bih[n];
}

// ---------------- GRU: 8-CTA cluster, R7 pull protocol + gi prefetch ----------------
__global__ void __cluster_dims__(8, 1, 1) __launch_bounds__(256, 1)
gru_kernel(const float* __restrict__ whh, const float* __restrict__ bhh,
           const float* __restrict__ h0) {
    __shared__ __align__(16) float hsh[H];
    __shared__ float ghsh[2][96];

    int tid = threadIdx.x;
    unsigned rank;
    asm("mov.u32 %0, %%cluster_ctarank;" : "=r"(rank));
    int g = tid >> 3, p = tid & 7;
    int jbase = (int)rank * 96 + g * 3;

    u64 wp[3][16];
    float bh[3];
#pragma unroll
    for (int c = 0; c < 3; c++) {
        int j = jbase + c;
        bh[c] = bhh[j];
        const float4* wr = (const float4*)(whh + (size_t)j * H + p * 32);
#pragma unroll
        for (int u = 0; u < 8; u++) {
            float4 v = wr[u];
            wp[c][2 * u]     = pk2(v.x, v.y);
            wp[c][2 * u + 1] = pk2(v.z, v.w);
        }
    }
    hsh[tid] = h0[tid];

    uint32_t radr[2][3];
#pragma unroll
    for (int par = 0; par < 2; par++)
#pragma unroll
        for (int c = 0; c < 3; c++) {
            int j = c * H + tid;
            radr[par][c] = mapa_u32(smem_u32(&ghsh[par][j % 96]), (uint32_t)(j / 96));
        }

    float gi0 = __ldg(g_gi + tid), gi1 = __ldg(g_gi + 256 + tid), gi2 = __ldg(g_gi + 512 + tid);

    for (int t = 0; t < S_SENT; t++) {
        __syncthreads();
        int par = t & 1;

        u64 hvp[16];
        const float4* hp = (const float4*)(hsh + p * 32);
#pragma unroll
        for (int u = 0; u < 8; u++) {
            float4 v = hp[u];
            hvp[2 * u]     = pk2(v.x, v.y);
            hvp[2 * u + 1] = pk2(v.z, v.w);
        }
        u64 pa0 = 0ull, pa1 = 0ull, pa2 = 0ull;
#pragma unroll
        for (int u = 0; u < 16; u++) {
            pa0 = ffma2(wp[0][u], hvp[u], pa0);
            pa1 = ffma2(wp[1][u], hvp[u], pa1);
            pa2 = ffma2(wp[2][u], hvp[u], pa2);
        }
        float a0 = pairsum(pa0), a1 = pairsum(pa1), a2 = pairsum(pa2);
#pragma unroll
        for (int off = 4; off > 0; off >>= 1) {
            a0 += __shfl_down_sync(0xffffffffu, a0, off, 8);
            a1 += __shfl_down_sync(0xffffffffu, a1, off, 8);
            a2 += __shfl_down_sync(0xffffffffu, a2, off, 8);
        }
        if (p == 0) {
            ghsh[par][g * 3 + 0] = a0 + bh[0];
            ghsh[par][g * 3 + 1] = a1 + bh[1];
            ghsh[par][g * 3 + 2] = a2 + bh[2];
        }
        float ngi0 = 0.f, ngi1 = 0.f, ngi2 = 0.f;
        if (t + 1 < S_SENT) {
            const float* gnr = g_gi + (size_t)(t + 1) * NH3;
            ngi0 = __ldg(gnr + tid); ngi1 = __ldg(gnr + 256 + tid); ngi2 = __ldg(gnr + 512 + tid);
        }
        cluster_barrier();

        float gh0 = ld_remote(radr[par][0]);
        float gh1 = ld_remote(radr[par][1]);
        float gh2 = ld_remote(radr[par][2]);
        float hh = hsh[tid];
        float r = sigf(gi0 + gh0);
        float z = sigf(gi1 + gh1);
        float n = tanhf(gi2 + r * gh2);
        hsh[tid] = (1.0f - z) * n + z * hh;

        gi0 = ngi0; gi1 = ngi1; gi2 = ngi2;
    }
    __syncthreads();
    if (rank == 0) g_hT[tid] = hsh[tid];
}

// ---------------- final: topic, gate, classifier, softmax ----------------
__global__ void final_kernel(const float* __restrict__ DT,
                             const float* __restrict__ gate_W, const float* __restrict__ gate_U,
                             const float* __restrict__ gate_b,
                             const float* __restrict__ mlp_W, const float* __restrict__ mlp_b,
                             const float* __restrict__ out_W, const float* __restrict__ out_b,
                             float* __restrict__ out) {
    __shared__ float tsh[H], hsh[H], vsh[H], lg[NTGT];
    int tid = threadIdx.x;
    float acc = mlp_b[tid];
    const float* mr = mlp_W + (size_t)tid * NTOPIC;
#pragma unroll 4
    for (int k = 0; k < NTOPIC; k++) acc += mr[k] * DT[k];
    tsh[tid] = tanhf(acc);
    hsh[tid] = g_hT[tid];
    __syncthreads();
    float ga = gate_b[tid], gb = gate_b[tid + H];
    const float* wr = gate_W + (size_t)tid * H;
    const float* wr2 = gate_W + (size_t)(tid + H) * H;
    const float* ur = gate_U + (size_t)tid * H;
    const float* ur2 = gate_U + (size_t)(tid + H) * H;
#pragma unroll 4
    for (int k = 0; k < H; k++) {
        float hk = hsh[k], tk = tsh[k];
        ga += wr[k] * hk + ur[k] * tk;
        gb += wr2[k] * hk + ur2[k] * tk;
    }
    vsh[tid] = tanhf(sigf(ga) * hsh[tid] + sigf(gb) * tsh[tid]);
    __syncthreads();
    int wix = tid >> 5, lane = tid & 31;
    if (wix < NTGT) {
        float a = 0.f;
        for (int k = lane; k < H; k += 32) a += out_W[wix * H + k] * vsh[k];
#pragma unroll
        for (int off = 16; off > 0; off >>= 1) a += __shfl_down_sync(0xffffffffu, a, off);
        if (lane == 0) lg[wix] = a + out_b[wix];
    }
    __syncthreads();
    if (tid == 0) {
        float mx = lg[0];
        for (int i = 1; i < NTGT; i++) mx = fmaxf(mx, lg[i]);
        float s = 0.f, e[NTGT];
        for (int i = 0; i < NTGT; i++) { e[i] = expf(lg[i] - mx); s += e[i]; }
        for (int i = 0; i < NTGT; i++) out[i] = e[i] / s;
    }
}

extern "C" void kernel_launch(void* const* d_in, const int* in_sizes, int n_in,
                              void* d_out, int out_size) {
    const int*   sidx    = (const int*)  d_in[0];
    const int*   dep     = (const int*)  d_in[1];
    const float* DT      = (const float*)d_in[2];
    const float* h0      = (const float*)d_in[3];
    const float* idx2vec = (const float*)d_in[4];
    const float* q       = (const float*)d_in[5];
    const float* W       = (const float*)d_in[6];
    const float* U       = (const float*)d_in[7];
    const float* D       = (const float*)d_in[8];
    const float* b       = (const float*)d_in[9];
    const float* gru_wih = (const float*)d_in[10];
    const float* gru_whh = (const float*)d_in[11];
    const float* gru_bih = (const float*)d_in[12];
    const float* gru_bhh = (const float*)d_in[13];
    const float* gate_W  = (const float*)d_in[14];
    const float* gate_U  = (const float*)d_in[15];
    const float* gate_b  = (const float*)d_in[16];
    const float* mlp_W   = (const float*)d_in[17];
    const float* mlp_b   = (const float*)d_in[18];
    const float* out_W   = (const float*)d_in[19];
    const float* out_b   = (const float*)d_in[20];
    float* out = (float*)d_out;

    cudaFuncSetAttribute(tree_persist, cudaFuncAttributeMaxDynamicSharedMemorySize, TREE_SMEM);

    prep_kernel<<<10, NH3>>>(D, q);
    wx_mma<<<dim3(12, 512), 256>>>(sidx, dep, idx2vec, W, b);
    leaf_kernel<<<1024, 256>>>();

    tree_persist<<<128, 256, TREE_SMEM>>>(U);

    ab_mma<<<dim3(12, 8, 2), 256>>>(gru_wih);
    gi_combine_kernel<<<3072, 256>>>(gru_bih);

    gru_kernel<<<8, 256>>>(gru_whh, gru_bhh, h0);

    final_kernel<<<1, 256>>>(DT, gate_W, gate_U, gate_b, mlp_W, mlp_b, out_W, out_b, out);
}